// round 9
// baseline (speedup 1.0000x reference)
#include <cuda_runtime.h>
#include <cstdint>

// Problem constants
#define NPROB 2048      // B*S = 8*256
#define DD    128       // feature dim (m = n = 128)
#define NITER 20

// K = (SCALE/eps) * log2(e) = 3000 * log2(e)
#define KCOEF 4328.085098989891f
#define TWOK  8656.170197979782f
#define INVK  2.3105011120474482e-4f
// ot scale: n * SCALE / NPROB = 128*300/2048
#define OTSCALE 18.75f

#define NCOPY   32
#define TH_SKIP 34.0f            // keep terms within 2^-34 of true max
#define PLAN_TH -35.0f           // plan entries below 2^-35 dropped
#define E_TH    -39.0f
#define CTOL    1.0e-5f          // convergence tol on potentials (log2 units)
#define FIX_SCALE 1099511627776.0f // 2^40 fixed-point scale

__device__ unsigned long long g_accum[(size_t)NCOPY * DD * DD];
__device__ float g_ot[DD * DD];
// Sorted problem data (written by sort_kernel)
__device__ float g_kx[(size_t)NPROB * DD];
__device__ float g_ky[(size_t)NPROB * DD];
__device__ int   g_ox[(size_t)NPROB * DD];
__device__ int   g_oy[(size_t)NPROB * DD];

__device__ __forceinline__ float ex2f(float x) {
    float r; asm("ex2.approx.ftz.f32 %0, %1;" : "=f"(r) : "f"(x)); return r;
}
__device__ __forceinline__ float lg2f(float x) {
    float r; asm("lg2.approx.f32 %0, %1;" : "=f"(r) : "f"(x)); return r;
}
__device__ __forceinline__ float warp_max(float v) {
#pragma unroll
    for (int o = 16; o; o >>= 1) v = fmaxf(v, __shfl_xor_sync(0xffffffffu, v, o));
    return v;
}

// ---------------- Sort kernel: one block per problem, bitonic, write sorted ----------------
__global__ void __launch_bounds__(128) sort_kernel(const float* __restrict__ X,
                                                   const float* __restrict__ Y) {
    __shared__ float kx[DD], ky[DD];
    __shared__ int ox[DD], oy[DD];
    const int p = blockIdx.x;
    const int t = threadIdx.x;

    kx[t] = X[(size_t)p * DD + t]; ox[t] = t;
    ky[t] = Y[(size_t)p * DD + t]; oy[t] = t;
    __syncthreads();

    for (int k = 2; k <= DD; k <<= 1) {
        for (int j = k >> 1; j > 0; j >>= 1) {
            int prt = t ^ j;
            bool keep_small = ((t < prt) == ((t & k) == 0));
            float mkx = kx[t], pkx = kx[prt];
            int   mix = ox[t], pix = ox[prt];
            float mky = ky[t], pky = ky[prt];
            int   miy = oy[t], piy = oy[prt];
            __syncthreads();
            bool lessx = (mkx < pkx) || (mkx == pkx && mix < pix);
            bool takex = (lessx == keep_small);
            kx[t] = takex ? mkx : pkx;  ox[t] = takex ? mix : pix;
            bool lessy = (mky < pky) || (mky == pky && miy < piy);
            bool takey = (lessy == keep_small);
            ky[t] = takey ? mky : pky;  oy[t] = takey ? miy : piy;
            __syncthreads();
        }
    }
    g_kx[(size_t)p * DD + t] = kx[t];
    g_ky[(size_t)p * DD + t] = ky[t];
    g_ox[(size_t)p * DD + t] = ox[t];
    g_oy[(size_t)p * DD + t] = oy[t];
}

// ---------------- Warp-per-problem Sinkhorn: zero block barriers ----------------
#define WPB 4   // warps (problems) per block
__global__ void __launch_bounds__(32 * WPB, 6)
sinkhorn_warp_kernel() {
    __shared__ __align__(16) float2 s_y[WPB][DD];  // {sorted y, pot b}
    __shared__ __align__(16) float2 s_x[WPB][DD];  // {sorted x, pot a}
    __shared__ int s_oy[WPB][DD];

    const int w = threadIdx.x >> 5;
    const int lane = threadIdx.x & 31;
    const int p = blockIdx.x * WPB + w;
    const int base = 4 * lane;

    // Coalesced vector loads of this warp's problem (sorted)
    float4 xv = *reinterpret_cast<const float4*>(g_kx + (size_t)p * DD + base);
    float4 yv = *reinterpret_cast<const float4*>(g_ky + (size_t)p * DD + base);
    int4  oxv = *reinterpret_cast<const int4*>(g_ox + (size_t)p * DD + base);
    int4  oyv = *reinterpret_cast<const int4*>(g_oy + (size_t)p * DD + base);

    float x[4] = {xv.x, xv.y, xv.z, xv.w};
    float y[4] = {yv.x, yv.y, yv.z, yv.w};
    float a[4], b[4], tkx[4], tky[4];
#pragma unroll
    for (int k = 0; k < 4; ++k) {
        tkx[k] = TWOK * x[k];
        tky[k] = TWOK * y[k];
        a[k] = -KCOEF * x[k] * x[k];
        b[k] = -KCOEF * y[k] * y[k];
        s_x[w][base + k] = make_float2(x[k], a[k]);
        s_y[w][base + k] = make_float2(y[k], b[k]);
        s_oy[w][base + k] = (k == 0) ? oyv.x : (k == 1) ? oyv.y : (k == 2) ? oyv.z : oyv.w;
    }
    float wmy = 0.f, wmx = 0.f;   // max over j of (pot + K*coord^2); exactly 0 at init
    __syncwarp();

    for (int it = 0; it < NITER; ++it) {
        // ---- f-update: rows 4*lane..4*lane+3, reduce over s_y ----
        float m[4], lo = 1e30f, hi = -1e30f;
#pragma unroll
        for (int k = 0; k < 4; ++k) {
            float vst = fmaf(tkx[k], y[k], b[k]);   // own-position candidate (valid lower bd)
            float r = sqrtf(fmaf(x[k], x[k], (wmy + TH_SKIP - vst) * INVK)); // arg > 0 always
            lo = fminf(lo, x[k] - r);
            hi = fmaxf(hi, x[k] + r);
            m[k] = vst;
        }
        int jlo = 0, jhi = 0;
#pragma unroll
        for (int st = 128; st; st >>= 1) {
            int c = jlo + st;
            if (c <= DD && s_y[w][c - 1].x < lo) jlo = c;
            int c2 = jhi + st;
            if (c2 <= DD && s_y[w][c2 - 1].x <= hi) jhi = c2;
        }
        for (int j = jlo; j < jhi; ++j) {          // max pass (FMA pipe)
            float2 e = s_y[w][j];
#pragma unroll
            for (int k = 0; k < 4; ++k) m[k] = fmaxf(m[k], fmaf(tkx[k], e.x, e.y));
        }
        float s[4] = {0.f, 0.f, 0.f, 0.f};
        for (int j = jlo; j < jhi; ++j) {          // exp pass
            float2 e = s_y[w][j];
#pragma unroll
            for (int k = 0; k < 4; ++k) s[k] += ex2f(fmaf(tkx[k], e.x, e.y) - m[k]);
        }
        float amov = 0.f, wl = -1e30f;
#pragma unroll
        for (int k = 0; k < 4; ++k) {
            float an = -(7.0f + m[k] + lg2f(s[k]));
            amov = fmaxf(amov, fabsf(an - a[k]));
            a[k] = an;
            wl = fmaxf(wl, fmaf(KCOEF * x[k], x[k], an));
        }
        wmx = warp_max(wl);
#pragma unroll
        for (int k = 0; k < 4; ++k) s_x[w][base + k] = make_float2(x[k], a[k]);
        __syncwarp();

        // ---- g-update: cols 4*lane..4*lane+3, reduce over s_x ----
        float lo2 = 1e30f, hi2 = -1e30f;
#pragma unroll
        for (int k = 0; k < 4; ++k) {
            float vst = fmaf(tky[k], x[k], a[k]);
            float r = sqrtf(fmaf(y[k], y[k], (wmx + TH_SKIP - vst) * INVK));
            lo2 = fminf(lo2, y[k] - r);
            hi2 = fmaxf(hi2, y[k] + r);
            m[k] = vst;
        }
        jlo = 0; jhi = 0;
#pragma unroll
        for (int st = 128; st; st >>= 1) {
            int c = jlo + st;
            if (c <= DD && s_x[w][c - 1].x < lo2) jlo = c;
            int c2 = jhi + st;
            if (c2 <= DD && s_x[w][c2 - 1].x <= hi2) jhi = c2;
        }
        for (int j = jlo; j < jhi; ++j) {
            float2 e = s_x[w][j];
#pragma unroll
            for (int k = 0; k < 4; ++k) m[k] = fmaxf(m[k], fmaf(tky[k], e.x, e.y));
        }
        s[0] = s[1] = s[2] = s[3] = 0.f;
        for (int j = jlo; j < jhi; ++j) {
            float2 e = s_x[w][j];
#pragma unroll
            for (int k = 0; k < 4; ++k) s[k] += ex2f(fmaf(tky[k], e.x, e.y) - m[k]);
        }
        float bmov = 0.f;
        wl = -1e30f;
#pragma unroll
        for (int k = 0; k < 4; ++k) {
            float bn = -(7.0f + m[k] + lg2f(s[k]));
            bmov = fmaxf(bmov, fabsf(bn - b[k]));
            b[k] = bn;
            wl = fmaxf(wl, fmaf(KCOEF * y[k], y[k], bn));
        }
        wmy = warp_max(wl);
#pragma unroll
        for (int k = 0; k < 4; ++k) s_y[w][base + k] = make_float2(y[k], b[k]);
        __syncwarp();

        if (__all_sync(0xffffffffu, (amov <= CTOL) && (bmov <= CTOL))) break;
    }

    // ---- Plan accumulation: lane's 4 rows; fixed-point atomic adds ----
    // plan_rj = 2^(a_r + b_j + twoKx_r*y_j); window via (x-y)^2 bound per row.
    {
        unsigned long long* cp = g_accum + (size_t)(p & (NCOPY - 1)) * (DD * DD);
        float lo = 1e30f, hi = -1e30f;
#pragma unroll
        for (int k = 0; k < 4; ++k) {
            float r2 = fmaf(x[k], x[k], (wmy + a[k] - PLAN_TH) * INVK);
            float r = sqrtf(fmaxf(r2, 0.f));
            bool live = (r2 > 0.f);
            lo = fminf(lo, live ? x[k] - r : 1e30f);
            hi = fmaxf(hi, live ? x[k] + r : -1e30f);
        }
        int jlo = 0, jhi = 0;
#pragma unroll
        for (int st = 128; st; st >>= 1) {
            int c = jlo + st;
            if (c <= DD && s_y[w][c - 1].x < lo) jlo = c;
            int c2 = jhi + st;
            if (c2 <= DD && s_y[w][c2 - 1].x <= hi) jhi = c2;
        }
        int oi[4] = {oxv.x, oxv.y, oxv.z, oxv.w};
        for (int j = jlo; j < jhi; ++j) {
            float2 e = s_y[w][j];
            int col = s_oy[w][j];
#pragma unroll
            for (int k = 0; k < 4; ++k) {
                float E = fmaf(tkx[k], e.x, e.y) + a[k];
                if (E > E_TH)
                    atomicAdd(cp + (size_t)oi[k] * DD + col,
                              __float2ull_rn(ex2f(E) * FIX_SCALE));
            }
        }
    }
}

__global__ void __launch_bounds__(256) zero_accum_kernel() {
    const int idx = blockIdx.x * 256 + threadIdx.x;
    g_accum[idx] = 0ull;
}

// Sum 32 fixed-point copies (exact integer sum -> deterministic), scale, add delta.
__global__ void __launch_bounds__(256) reduce_b_kernel(const float* __restrict__ delta) {
    const int idx = blockIdx.x * 256 + threadIdx.x;
    unsigned long long tot = 0ull;
#pragma unroll
    for (int c = 0; c < NCOPY; ++c) tot += g_accum[(size_t)c * (DD * DD) + idx];
    g_ot[idx] = (float)((double)tot * ((double)OTSCALE / (double)FIX_SCALE)) + delta[idx];
}

// out[p, :] = X[p, :] @ ot  -- measured-best config (11.0us, occ 78%).
__global__ void __launch_bounds__(128) gemm_out_kernel(const float* __restrict__ X,
                                                       float* __restrict__ out) {
    __shared__ float xs[DD];
    const int p = blockIdx.x;
    const int t = threadIdx.x;
    xs[t] = X[(size_t)p * DD + t];
    __syncthreads();
    float a0 = 0.f, a1 = 0.f, a2 = 0.f, a3 = 0.f;
#pragma unroll 8
    for (int i = 0; i < DD; i += 4) {
        a0 = fmaf(xs[i + 0], g_ot[(i + 0) * DD + t], a0);
        a1 = fmaf(xs[i + 1], g_ot[(i + 1) * DD + t], a1);
        a2 = fmaf(xs[i + 2], g_ot[(i + 2) * DD + t], a2);
        a3 = fmaf(xs[i + 3], g_ot[(i + 3) * DD + t], a3);
    }
    out[(size_t)p * DD + t] = (a0 + a1) + (a2 + a3);
}

extern "C" void kernel_launch(void* const* d_in, const int* in_sizes, int n_in,
                              void* d_out, int out_size) {
    const float* X = (const float*)d_in[0];      // [8,256,128]
    const float* Y = (const float*)d_in[1];      // [8,256,128]
    const float* delta = (const float*)d_in[2];  // [128,128]
    float* out = (float*)d_out;                  // [8,256,128] float32

    zero_accum_kernel<<<(NCOPY * DD * DD) / 256, 256>>>();
    sort_kernel<<<NPROB, 128>>>(X, Y);
    sinkhorn_warp_kernel<<<NPROB / WPB, 32 * WPB>>>();
    reduce_b_kernel<<<(DD * DD) / 256, 256>>>(delta);
    gemm_out_kernel<<<NPROB, 128>>>(X, out);
}

// round 10
// speedup vs baseline: 1.3809x; 1.3809x over previous
#include <cuda_runtime.h>
#include <cstdint>

// Problem constants
#define NPROB 2048      // B*S = 8*256
#define DD    128       // feature dim (m = n = 128)
#define NITER 20
#define NB    128       // LUT bins

// K = (SCALE/eps) * log2(e) = 3000 * log2(e)
#define KCOEF 4328.085098989891f
#define TWOK  8656.170197979782f
#define INVK  2.3105011120474482e-4f
// ot scale: n * SCALE / NPROB = 128*300/2048
#define OTSCALE 18.75f

#define NCOPY   32
#define TH_SKIP 34.0f            // keep terms within 2^-34 of est. max
#define SMIN    2.44140625e-4f   // 2^-12 guard
#define SMAX    4096.0f          // 2^12 guard
#define PLAN_TH -35.0f           // plan entries below 2^-35 dropped
#define E_TH    -39.0f
#define CTOL    1.0e-5f          // convergence tol (log2 units)
#define FIX_SCALE 1099511627776.0f // 2^40 fixed-point scale

__device__ unsigned long long g_accum[(size_t)NCOPY * DD * DD];
__device__ float g_ot[DD * DD];

__device__ __forceinline__ float ex2f(float x) {
    float r; asm("ex2.approx.ftz.f32 %0, %1;" : "=f"(r) : "f"(x)); return r;
}
__device__ __forceinline__ float lg2f(float x) {
    float r; asm("lg2.approx.f32 %0, %1;" : "=f"(r) : "f"(x)); return r;
}
__device__ __forceinline__ float warp_max(float v) {
#pragma unroll
    for (int o = 16; o; o >>= 1) v = fmaxf(v, __shfl_xor_sync(0xffffffffu, v, o));
    return v;
}

// Full two-pass LSE sweep (exact fallback; warp-uniform call).
__device__ __forceinline__ float lse_full(const float2* __restrict__ arr, float twoKc) {
    const float4* a4 = reinterpret_cast<const float4*>(arr);
    float m0 = -1e30f, m1 = -1e30f, m2 = -1e30f, m3 = -1e30f;
#pragma unroll 8
    for (int q = 0; q < DD / 4; ++q) {
        float4 u = a4[2 * q];
        float4 w = a4[2 * q + 1];
        m0 = fmaxf(m0, fmaf(twoKc, u.x, u.y));
        m1 = fmaxf(m1, fmaf(twoKc, u.z, u.w));
        m2 = fmaxf(m2, fmaf(twoKc, w.x, w.y));
        m3 = fmaxf(m3, fmaf(twoKc, w.z, w.w));
    }
    float mx = fmaxf(fmaxf(m0, m1), fmaxf(m2, m3));
    float s0 = 0.f, s1 = 0.f, s2 = 0.f, s3 = 0.f;
#pragma unroll 8
    for (int q = 0; q < DD / 4; ++q) {
        float4 u = a4[2 * q];
        float4 w = a4[2 * q + 1];
        s0 += ex2f(fmaf(twoKc, u.x, u.y) - mx);
        s1 += ex2f(fmaf(twoKc, u.z, u.w) - mx);
        s2 += ex2f(fmaf(twoKc, w.x, w.y) - mx);
        s3 += ex2f(fmaf(twoKc, w.z, w.w) - mx);
    }
    float s = (s0 + s1) + (s2 + s3);
    return -(7.0f + mx + lg2f(s));
}

// Element window [lo,hi] -> element index range via bin LUT (O(1), 2 LDS).
// LUT[q] = #keys < kmin + q*w;  widened by 1 bin each side for rounding safety.
// Any over-inclusion is harmless: every element is a legitimate LSE term.
__device__ __forceinline__ void lut_range(const int* __restrict__ lut,
                                          float kmin, float invw,
                                          float lo, float hi,
                                          int& jlo, int& jhi) {
    int bl = __float2int_rd((lo - kmin) * invw) - 1;
    bl = bl < 0 ? 0 : (bl > NB ? NB : bl);
    int bh = __float2int_rd((hi - kmin) * invw) + 2;
    bh = bh < 0 ? 0 : (bh > NB ? NB : bh);
    jlo = lut[bl];
    jhi = lut[bh];
}

__global__ void __launch_bounds__(128) sinkhorn_kernel(const float* __restrict__ X,
                                                       const float* __restrict__ Y) {
    __shared__ __align__(16) float2 sx[DD];   // {sorted x, pot a}
    __shared__ __align__(16) float2 sy[DD];   // {sorted y, pot b}
    __shared__ int ox[DD], oy[DD];            // original indices
    __shared__ __align__(16) float kx[DD], ky[DD];   // sorted coords
    __shared__ int lutx[NB + 1], luty[NB + 1];
    __shared__ float wxp[4], wyp[4];          // per-warp maxes of w = pot + K*coord^2
    __shared__ float sc[4];                   // kminx, invwx, kminy, invwy

    const int p = blockIdx.x;
    const int t = threadIdx.x;

    kx[t] = X[(size_t)p * DD + t]; ox[t] = t;
    ky[t] = Y[(size_t)p * DD + t]; oy[t] = t;
    if (t < 4) { wxp[t] = 0.f; wyp[t] = 0.f; }   // w == 0 at init
    __syncthreads();

    // Bitonic sort both (kx,ox) and (ky,oy) ascending; index tiebreak.
    for (int k = 2; k <= DD; k <<= 1) {
        for (int j = k >> 1; j > 0; j >>= 1) {
            int prt = t ^ j;
            bool keep_small = ((t < prt) == ((t & k) == 0));
            float mkx = kx[t], pkx = kx[prt];
            int   mix = ox[t], pix = ox[prt];
            float mky = ky[t], pky = ky[prt];
            int   miy = oy[t], piy = oy[prt];
            __syncthreads();
            bool lessx = (mkx < pkx) || (mkx == pkx && mix < pix);
            bool takex = (lessx == keep_small);
            kx[t] = takex ? mkx : pkx;  ox[t] = takex ? mix : pix;
            bool lessy = (mky < pky) || (mky == pky && miy < piy);
            bool takey = (lessy == keep_small);
            ky[t] = takey ? mky : pky;  oy[t] = takey ? miy : piy;
            __syncthreads();
        }
    }

    // Build bin LUTs (once). Bin widths from sorted extremes.
    if (t == 0) {
        sc[0] = kx[0];  sc[1] = (float)NB / (kx[DD - 1] - kx[0]);
        sc[2] = ky[0];  sc[3] = (float)NB / (ky[DD - 1] - ky[0]);
        lutx[NB] = DD;  luty[NB] = DD;
    }
    __syncthreads();
    {
        float wx = 1.0f / sc[1], wy = 1.0f / sc[3];
        float bx = sc[0] + (float)t * wx;
        float by = sc[2] + (float)t * wy;
        int cx = 0, cy = 0;
#pragma unroll
        for (int st = 128; st; st >>= 1) {
            int c = cx + st;
            if (c <= DD && kx[c - 1] < bx) cx = c;
            int c2 = cy + st;
            if (c2 <= DD && ky[c2 - 1] < by) cy = c2;
        }
        lutx[t] = cx;
        luty[t] = cy;
    }

    const float x = kx[t];
    const float y = ky[t];
    const float twoKx = TWOK * x;
    const float twoKy = TWOK * y;
    const float Kx2 = KCOEF * x * x;
    const float Ky2 = KCOEF * y * y;
    float areg = -Kx2;
    float breg = -Ky2;
    sx[t] = make_float2(x, areg);
    sy[t] = make_float2(y, breg);
    __syncthreads();

    const float kminy = sc[2], invwy = sc[3];
    const float kminx = sc[0], invwx = sc[1];

    for (int it = 0; it < NITER; ++it) {
        // ---- f-update (rows; reduce over sy) ----
        float a_new;
        {
            bool full = (it == 0);
            if (!full) {
                float wmaxy = fmaxf(fmaxf(wyp[0], wyp[1]), fmaxf(wyp[2], wyp[3]));
                float mx_est = -7.0f - areg;
                float r2 = fmaf(x, x, (wmaxy + 7.0f + TH_SKIP + areg) * INVK);
                float r = sqrtf(fmaxf(r2, 0.f));
                float lo = x - r, hi = x + r;
#pragma unroll
                for (int o = 1; o <= 4; o <<= 1) {          // 8-lane union
                    lo = fminf(lo, __shfl_xor_sync(0xffffffffu, lo, o));
                    hi = fmaxf(hi, __shfl_xor_sync(0xffffffffu, hi, o));
                }
                int jlo, jhi;
                lut_range(luty, kminy, invwy, lo, hi, jlo, jhi);
                int G0 = jlo >> 2, G1 = (jhi + 3) >> 2;
                const float4* a4 = reinterpret_cast<const float4*>(sy);
                float s0 = 0.f, s1 = 0.f;
                for (int g = G0; g < G1; ++g) {             // uniform, branch-free
                    float4 u = a4[2 * g];
                    float4 w = a4[2 * g + 1];
                    s0 += ex2f(fmaf(twoKx, u.x, u.y) - mx_est);
                    s1 += ex2f(fmaf(twoKx, u.z, u.w) - mx_est);
                    s0 += ex2f(fmaf(twoKx, w.x, w.y) - mx_est);
                    s1 += ex2f(fmaf(twoKx, w.z, w.w) - mx_est);
                }
                float s = s0 + s1;
                a_new = -(7.0f + mx_est + lg2f(s));
                bool bad = !(s >= SMIN && s <= SMAX);
                full = __any_sync(0xffffffffu, bad);
            }
            if (full) a_new = lse_full(sy, twoKx);
        }
        float amov = fabsf(a_new - areg);
        areg = a_new;
        sx[t].y = a_new;
        float wm = warp_max(a_new + Kx2);
        if ((t & 31) == 0) wxp[t >> 5] = wm;
        __syncthreads();

        // ---- g-update (cols; reduce over sx) ----
        float b_new;
        {
            bool full = (it == 0);
            if (!full) {
                float wmaxx = fmaxf(fmaxf(wxp[0], wxp[1]), fmaxf(wxp[2], wxp[3]));
                float my_est = -7.0f - breg;
                float r2 = fmaf(y, y, (wmaxx + 7.0f + TH_SKIP + breg) * INVK);
                float r = sqrtf(fmaxf(r2, 0.f));
                float lo = y - r, hi = y + r;
#pragma unroll
                for (int o = 1; o <= 4; o <<= 1) {
                    lo = fminf(lo, __shfl_xor_sync(0xffffffffu, lo, o));
                    hi = fmaxf(hi, __shfl_xor_sync(0xffffffffu, hi, o));
                }
                int jlo, jhi;
                lut_range(lutx, kminx, invwx, lo, hi, jlo, jhi);
                int G0 = jlo >> 2, G1 = (jhi + 3) >> 2;
                const float4* a4 = reinterpret_cast<const float4*>(sx);
                float s0 = 0.f, s1 = 0.f;
                for (int g = G0; g < G1; ++g) {
                    float4 u = a4[2 * g];
                    float4 w = a4[2 * g + 1];
                    s0 += ex2f(fmaf(twoKy, u.x, u.y) - my_est);
                    s1 += ex2f(fmaf(twoKy, u.z, u.w) - my_est);
                    s0 += ex2f(fmaf(twoKy, w.x, w.y) - my_est);
                    s1 += ex2f(fmaf(twoKy, w.z, w.w) - my_est);
                }
                float s = s0 + s1;
                b_new = -(7.0f + my_est + lg2f(s));
                bool bad = !(s >= SMIN && s <= SMAX);
                full = __any_sync(0xffffffffu, bad);
            }
            if (full) b_new = lse_full(sx, twoKy);
        }
        float bmov = fabsf(b_new - breg);
        breg = b_new;
        sy[t].y = b_new;
        float wn = warp_max(b_new + Ky2);
        if ((t & 31) == 0) wyp[t >> 5] = wn;

        int moved = (amov > CTOL) || (bmov > CTOL);
        if (!__syncthreads_or(moved)) break;
    }

    // ---- Plan accumulation: thread t = sorted row t; fixed-point atomic adds ----
    {
        const int oi = ox[t];
        unsigned long long* rowp =
            g_accum + (size_t)(p & (NCOPY - 1)) * (DD * DD) + (size_t)oi * DD;
        float wmaxy = fmaxf(fmaxf(wyp[0], wyp[1]), fmaxf(wyp[2], wyp[3]));
        float r2 = fmaf(x, x, (wmaxy + areg - PLAN_TH) * INVK);
        float r = sqrtf(fmaxf(r2, 0.f));
        float lo = x - r, hi = x + r;
#pragma unroll
        for (int o = 1; o <= 4; o <<= 1) {
            lo = fminf(lo, __shfl_xor_sync(0xffffffffu, lo, o));
            hi = fmaxf(hi, __shfl_xor_sync(0xffffffffu, hi, o));
        }
        int jlo, jhi;
        lut_range(luty, kminy, invwy, lo, hi, jlo, jhi);
        int G0 = jlo >> 2, G1 = (jhi + 3) >> 2;
        const float4* a4 = reinterpret_cast<const float4*>(sy);
        for (int g = G0; g < G1; ++g) {
            float4 u = a4[2 * g];
            float4 w = a4[2 * g + 1];
            float E0 = fmaf(twoKx, u.x, u.y) + areg;
            float E1 = fmaf(twoKx, u.z, u.w) + areg;
            float E2 = fmaf(twoKx, w.x, w.y) + areg;
            float E3 = fmaf(twoKx, w.z, w.w) + areg;
            if (E0 > E_TH)
                atomicAdd(rowp + oy[4 * g + 0], __float2ull_rn(ex2f(E0) * FIX_SCALE));
            if (E1 > E_TH)
                atomicAdd(rowp + oy[4 * g + 1], __float2ull_rn(ex2f(E1) * FIX_SCALE));
            if (E2 > E_TH)
                atomicAdd(rowp + oy[4 * g + 2], __float2ull_rn(ex2f(E2) * FIX_SCALE));
            if (E3 > E_TH)
                atomicAdd(rowp + oy[4 * g + 3], __float2ull_rn(ex2f(E3) * FIX_SCALE));
        }
    }
}

__global__ void __launch_bounds__(256) zero_accum_kernel() {
    const int idx = blockIdx.x * 256 + threadIdx.x;
    g_accum[idx] = 0ull;
}

// Sum 32 fixed-point copies (exact integer sum -> deterministic), scale, add delta.
__global__ void __launch_bounds__(256) reduce_b_kernel(const float* __restrict__ delta) {
    const int idx = blockIdx.x * 256 + threadIdx.x;
    unsigned long long tot = 0ull;
#pragma unroll
    for (int c = 0; c < NCOPY; ++c) tot += g_accum[(size_t)c * (DD * DD) + idx];
    g_ot[idx] = (float)((double)tot * ((double)OTSCALE / (double)FIX_SCALE)) + delta[idx];
}

// out[p, :] = X[p, :] @ ot  -- measured-best config (11.0us, occ 78%).
__global__ void __launch_bounds__(128) gemm_out_kernel(const float* __restrict__ X,
                                                       float* __restrict__ out) {
    __shared__ float xs[DD];
    const int p = blockIdx.x;
    const int t = threadIdx.x;
    xs[t] = X[(size_t)p * DD + t];
    __syncthreads();
    float a0 = 0.f, a1 = 0.f, a2 = 0.f, a3 = 0.f;
#pragma unroll 8
    for (int i = 0; i < DD; i += 4) {
        a0 = fmaf(xs[i + 0], g_ot[(i + 0) * DD + t], a0);
        a1 = fmaf(xs[i + 1], g_ot[(i + 1) * DD + t], a1);
        a2 = fmaf(xs[i + 2], g_ot[(i + 2) * DD + t], a2);
        a3 = fmaf(xs[i + 3], g_ot[(i + 3) * DD + t], a3);
    }
    out[(size_t)p * DD + t] = (a0 + a1) + (a2 + a3);
}

extern "C" void kernel_launch(void* const* d_in, const int* in_sizes, int n_in,
                              void* d_out, int out_size) {
    const float* X = (const float*)d_in[0];      // [8,256,128]
    const float* Y = (const float*)d_in[1];      // [8,256,128]
    const float* delta = (const float*)d_in[2];  // [128,128]
    float* out = (float*)d_out;                  // [8,256,128] float32

    zero_accum_kernel<<<(NCOPY * DD * DD) / 256, 256>>>();
    sinkhorn_kernel<<<NPROB, 128>>>(X, Y);
    reduce_b_kernel<<<(DD * DD) / 256, 256>>>(delta);
    gemm_out_kernel<<<NPROB, 128>>>(X, out);
}